// round 15
// baseline (speedup 1.0000x reference)
#include <cuda_runtime.h>
#include <cstdint>

#define DD 128
#define NMAX 50176
#define EMAX 800256

// ---------------- scratch (__device__ globals; no allocation) ----------------
__device__ float g_ht[(size_t)NMAX * DD];   // post-linear h
__device__ float g_h2[(size_t)NMAX * DD];   // aggregated h (next gemm input)
__device__ float g_sl[NMAX], g_sr[NMAX];
__device__ float g_ew[EMAX];                // cached edge scores e = sl[i]+sr[j]+b
__device__ int   g_deg[NMAX];
__device__ int   g_off[NMAX + 1];
__device__ int   g_pos[NMAX];
__device__ int   g_col[EMAX];

// ---------------- CSR build ----------------
__global__ void k_count(const int* __restrict__ src, int E) {
    int i = blockIdx.x * blockDim.x + threadIdx.x;
    int e4 = E >> 2;
    if (i < e4) {
        int4 s = ((const int4*)src)[i];
        atomicAdd(&g_deg[s.x], 1);
        atomicAdd(&g_deg[s.y], 1);
        atomicAdd(&g_deg[s.z], 1);
        atomicAdd(&g_deg[s.w], 1);
    } else {
        int k = e4 * 4 + (i - e4);
        if (k < E) atomicAdd(&g_deg[src[k]], 1);
    }
}
__global__ __launch_bounds__(1024) void k_scan(int N, int E) {
    __shared__ int sh[1024];
    int tid = threadIdx.x;
    int per = (N + 1023) >> 10;
    int s = tid * per;
    int e = s + per; if (e > N) e = N;
    int sum = 0;
    for (int i = s; i < e; i++) sum += g_deg[i];
    sh[tid] = sum;
    __syncthreads();
    for (int o = 1; o < 1024; o <<= 1) {
        int t = (tid >= o) ? sh[tid - o] : 0;
        __syncthreads();
        sh[tid] += t;
        __syncthreads();
    }
    int run = sh[tid] - sum;
    for (int i = s; i < e; i++) { g_off[i] = run; g_pos[i] = run; run += g_deg[i]; }
    if (tid == 1023) g_off[N] = E;
}
__global__ void k_scatter(const int* __restrict__ src, const int* __restrict__ dst, int E) {
    int i = blockIdx.x * blockDim.x + threadIdx.x;
    int e4 = E >> 2;
    if (i < e4) {
        int4 s = ((const int4*)src)[i];
        int4 d = ((const int4*)dst)[i];
        g_col[atomicAdd(&g_pos[s.x], 1)] = d.x;
        g_col[atomicAdd(&g_pos[s.y], 1)] = d.y;
        g_col[atomicAdd(&g_pos[s.z], 1)] = d.z;
        g_col[atomicAdd(&g_pos[s.w], 1)] = d.w;
    } else {
        int k = e4 * 4 + (i - e4);
        if (k < E) g_col[atomicAdd(&g_pos[src[k]], 1)] = dst[k];
    }
}

// ---------------- GEMM: ht = leaky_relu(in @ W + b) + fused dots --------------
__global__ __launch_bounds__(256, 3) void k_gemm(
    const float* __restrict__ in,
    const float* __restrict__ W, const float* __restrict__ bias,
    const float* __restrict__ aw, int M)
{
    __shared__ float ws[64 * 128];   // 32 KB  W chunk [64k x 128n]
    __shared__ float hs[64 * 64];    // 16 KB  h tile  [64rows x 64k]

    int tid = threadIdx.x, warp = tid >> 5, lane = tid & 31;
    int r0 = blockIdx.x * 64;
    int c4 = lane * 4;

    float4 acc[8];
#pragma unroll
    for (int r = 0; r < 8; r++) acc[r] = make_float4(0.f, 0.f, 0.f, 0.f);

    for (int kc = 0; kc < DD; kc += 64) {
        const float4* wsrc = (const float4*)(W + (size_t)kc * DD);
        float4* wdst = (float4*)ws;
#pragma unroll
        for (int i = 0; i < 8; i++) wdst[tid + i * 256] = wsrc[tid + i * 256];
#pragma unroll
        for (int i = 0; i < 4; i++) {
            int idx = tid + i * 256;
            int row = idx >> 4;
            int c = idx & 15;
            float4 v = make_float4(0.f, 0.f, 0.f, 0.f);
            if (r0 + row < M)
                v = *(const float4*)(in + (size_t)(r0 + row) * DD + kc + c * 4);
            *(float4*)(hs + row * 64 + c * 4) = v;
        }
        __syncthreads();
        int wr = warp * 8;
#pragma unroll 8
        for (int k = 0; k < 64; k++) {
            float4 w4 = *(const float4*)(ws + k * DD + c4);
#pragma unroll
            for (int r = 0; r < 8; r++) {
                float a = hs[(wr + r) * 64 + k];
                acc[r].x += a * w4.x; acc[r].y += a * w4.y;
                acc[r].z += a * w4.z; acc[r].w += a * w4.w;
            }
        }
        __syncthreads();
    }

    float4 bb = *(const float4*)(bias + c4);
    float4 al = *(const float4*)(aw + c4);
    float4 ar = *(const float4*)(aw + DD + c4);
#pragma unroll
    for (int r = 0; r < 8; r++) {
        int row = r0 + warp * 8 + r;
        if (row < M) {
            float4 v = acc[r];
            v.x += bb.x; v.x = v.x > 0.f ? v.x : 0.2f * v.x;
            v.y += bb.y; v.y = v.y > 0.f ? v.y : 0.2f * v.y;
            v.z += bb.z; v.z = v.z > 0.f ? v.z : 0.2f * v.z;
            v.w += bb.w; v.w = v.w > 0.f ? v.w : 0.2f * v.w;
            *(float4*)(g_ht + (size_t)row * DD + c4) = v;
            float dl = v.x * al.x + v.y * al.y + v.z * al.z + v.w * al.w;
            float dr = v.x * ar.x + v.y * ar.y + v.z * ar.z + v.w * ar.w;
#pragma unroll
            for (int o = 16; o; o >>= 1) {
                dl += __shfl_xor_sync(0xffffffffu, dl, o);
                dr += __shfl_xor_sync(0xffffffffu, dr, o);
            }
            if (lane == 0) { g_sl[row] = dl; g_sr[row] = dr; }
        }
    }
}

// ---------------- aggregation (warp per node; MLP-4 unrolled pass 2) ----------
__global__ __launch_bounds__(256) void k_agg(
    float* __restrict__ out, const float* __restrict__ abp, int N)
{
    const float* ht = g_ht;
    int gw = (blockIdx.x * blockDim.x + threadIdx.x) >> 5;
    int lane = threadIdx.x & 31;
    if (gw >= N) return;

    int base = g_off[gw], end = g_off[gw + 1];
    int c4 = lane * 4;
    float4 acc = make_float4(0.f, 0.f, 0.f, 0.f);

    if (end > base) {
        float ab = *abp;
        float sli = g_sl[gw];
        // pass 1: online softmax stats; cache e (coalesced 128B warp writes)
        float m = -1e30f, s = 0.f;
        for (int k = base + lane; k < end; k += 32) {
            int d = g_col[k];
            float e = sli + g_sr[d] + ab;
            g_ew[k] = e;
            if (e > m) { s = s * __expf(m - e) + 1.f; m = e; }
            else        { s += __expf(e - m); }
        }
#pragma unroll
        for (int o = 16; o; o >>= 1) {
            float mo = __shfl_xor_sync(0xffffffffu, m, o);
            float so = __shfl_xor_sync(0xffffffffu, s, o);
            float mn = fmaxf(m, mo);
            s = s * __expf(m - mn) + so * __expf(mo - mn);
            m = mn;
        }
        float inv = 1.f / s;

        // pass 2: unroll-by-4 — batch independent loads to raise MLP
        int k = base;
        for (; k + 4 <= end; k += 4) {
            int d0 = g_col[k + 0];
            int d1 = g_col[k + 1];
            int d2 = g_col[k + 2];
            int d3 = g_col[k + 3];
            float e0 = g_ew[k + 0], e1 = g_ew[k + 1];
            float e2 = g_ew[k + 2], e3 = g_ew[k + 3];
            float4 h0 = *(const float4*)(ht + (size_t)d0 * DD + c4);
            float4 h1 = *(const float4*)(ht + (size_t)d1 * DD + c4);
            float4 h2 = *(const float4*)(ht + (size_t)d2 * DD + c4);
            float4 h3 = *(const float4*)(ht + (size_t)d3 * DD + c4);
            float w0 = __expf(e0 - m) * inv;
            float w1 = __expf(e1 - m) * inv;
            float w2 = __expf(e2 - m) * inv;
            float w3 = __expf(e3 - m) * inv;
            acc.x += w0 * h0.x; acc.y += w0 * h0.y; acc.z += w0 * h0.z; acc.w += w0 * h0.w;
            acc.x += w1 * h1.x; acc.y += w1 * h1.y; acc.z += w1 * h1.z; acc.w += w1 * h1.w;
            acc.x += w2 * h2.x; acc.y += w2 * h2.y; acc.z += w2 * h2.z; acc.w += w2 * h2.w;
            acc.x += w3 * h3.x; acc.y += w3 * h3.y; acc.z += w3 * h3.z; acc.w += w3 * h3.w;
        }
        for (; k < end; k++) {
            int d = g_col[k];
            float w = __expf(g_ew[k] - m) * inv;
            float4 hv = *(const float4*)(ht + (size_t)d * DD + c4);
            acc.x += w * hv.x; acc.y += w * hv.y;
            acc.z += w * hv.z; acc.w += w * hv.w;
        }
    }
    acc.x = fmaxf(acc.x, 0.f);
    acc.y = fmaxf(acc.y, 0.f);
    acc.z = fmaxf(acc.z, 0.f);
    acc.w = fmaxf(acc.w, 0.f);
    *(float4*)(out + (size_t)gw * DD + c4) = acc;
}

// ---------------- launch: single stream -------------------------------------
extern "C" void kernel_launch(void* const* d_in, const int* in_sizes, int n_in,
                              void* d_out, int out_size)
{
    const float* x      = (const float*)d_in[0];
    const int*   esrc   = (const int*)d_in[1];
    const int*   edst   = (const int*)d_in[2];
    const float* lin_w  = (const float*)d_in[3];
    const float* lin_b  = (const float*)d_in[4];
    const float* attn_w = (const float*)d_in[5];
    const float* attn_b = (const float*)d_in[6];

    int N = in_sizes[0] / DD;
    int E = in_sizes[1];

    void* degp = nullptr;
    cudaGetSymbolAddress(&degp, g_deg);
    float* h2p = nullptr;
    cudaGetSymbolAddress((void**)&h2p, g_h2);

    int gB = (N + 63) / 64;
    int aB = (N + 7) / 8;
    int cT = (E >> 2) + (E & 3);

    cudaMemsetAsync(degp, 0, (size_t)N * sizeof(int), 0);
    k_count<<<(cT + 255) / 256, 256>>>(esrc, E);
    k_scan<<<1, 1024>>>(N, E);
    k_scatter<<<(cT + 255) / 256, 256>>>(esrc, edst, E);

    k_gemm<<<gB, 256>>>(x, lin_w, lin_b, attn_w, N);
    k_agg<<<aB, 256>>>(h2p, attn_b + 0, N);
    k_gemm<<<gB, 256>>>(h2p, lin_w + (size_t)1 * DD * DD, lin_b + DD,
                        attn_w + (size_t)1 * 2 * DD, N);
    k_agg<<<aB, 256>>>(h2p, attn_b + 1, N);
    k_gemm<<<gB, 256>>>(h2p, lin_w + (size_t)2 * DD * DD, lin_b + 2 * DD,
                        attn_w + (size_t)2 * 2 * DD, N);
    k_agg<<<aB, 256>>>((float*)d_out, attn_b + 2, N);
}